// round 14
// baseline (speedup 1.0000x reference)
#include <cuda_runtime.h>
#include <cuda_bf16.h>
#include <cstdint>

#define DIM 128
#define TILE96 96
#define MAX_N 1000000
#define MAX_B 20000

__device__ unsigned short g_seg[MAX_N];   // row -> segment id
__device__ float g_segsum[MAX_B];         // per-segment sum of exp

// ---------------- smem layout (kernel 1) ----------------
// W_hi 32K | W_lo 32K | 2 A-slots (hi 24K + lo 24K each) | bk | c2 | mbar | sred | es
#define OFF_W_HI   0
#define OFF_W_LO   32768
#define OFF_SLOT0  65536
#define SLOT_BYTES 49152
#define OFF_BK     163840          // b[c] * 2*log2(e)
#define OFF_C2     164352          // -2 * ctx[c]
#define OFF_MBAR   164864          // full[0..1] @ +0, empty[0..1] @ +16
#define OFF_SRED   164928          // float [2][96] score halves
#define OFF_ES     165696          // float [96] exp(score)
#define SMEM_TOTAL (165696 + 512)

#define N_CONS 384                 // 12 consumer warps (3 per SMSP)
#define N_PROD 128                 // 4 producer warps
#define N_THREADS (N_CONS + N_PROD)

#define K2LOG2E 2.8853900817779268f

// ---------------- helpers ----------------
__device__ __forceinline__ uint32_t smem_to_u32(const void* p) {
    uint32_t a;
    asm("{ .reg .u64 t; cvta.to.shared.u64 t, %1; cvt.u32.u64 %0, t; }"
        : "=r"(a) : "l"(p));
    return a;
}

__device__ __forceinline__ float ex2f(float x) {
    float y; asm("ex2.approx.f32 %0, %1;" : "=f"(y) : "f"(x)); return y;
}
__device__ __forceinline__ float rcpf(float x) {
    float y; asm("rcp.approx.f32 %0, %1;" : "=f"(y) : "f"(x)); return y;
}

// swizzled bf16 tile address: row-major, 256B/row (128 bf16), 16B chunks XOR'd by row&7
__device__ __forceinline__ uint32_t sw_addr(uint32_t base, int row, int kchunk) {
    return base + (uint32_t)row * 256u + (uint32_t)((kchunk ^ (row & 7)) << 4);
}

__device__ __forceinline__ void ldsm4(uint32_t* r, uint32_t addr) {
    asm volatile("ldmatrix.sync.aligned.m8n8.x4.shared.b16 {%0,%1,%2,%3}, [%4];"
        : "=r"(r[0]), "=r"(r[1]), "=r"(r[2]), "=r"(r[3]) : "r"(addr));
}

__device__ __forceinline__ void mma_bf16(float* d, const uint32_t* a, const uint32_t* b) {
    asm volatile(
        "mma.sync.aligned.m16n8k16.row.col.f32.bf16.bf16.f32 "
        "{%0,%1,%2,%3}, {%4,%5,%6,%7}, {%8,%9}, {%0,%1,%2,%3};"
        : "+f"(d[0]), "+f"(d[1]), "+f"(d[2]), "+f"(d[3])
        : "r"(a[0]), "r"(a[1]), "r"(a[2]), "r"(a[3]), "r"(b[0]), "r"(b[1]));
}

#define MBARRIER_INIT(mbar, count) \
    asm volatile("mbarrier.init.shared.b64 [%0], %1;" \
        :: "r"((uint32_t)(mbar)), "r"((uint32_t)(count)) : "memory")

#define MBARRIER_ARRIVE(mbar) \
    asm volatile("mbarrier.arrive.release.cta.shared.b64 _, [%0];" \
        :: "r"((uint32_t)(mbar)) : "memory")

#define MBARRIER_WAIT_PARITY(mbar, parity) do { \
    uint32_t _m = (uint32_t)(mbar), _p = (uint32_t)(parity), _d; \
    asm volatile( \
        "{\n\t.reg .pred p;\n\t" \
        "mbarrier.try_wait.parity.acquire.cta.shared::cta.b64 p, [%1], %2;\n\t" \
        "selp.b32 %0, 1, 0, p;\n\t}" \
        : "=r"(_d) : "r"(_m), "r"(_p) : "memory"); \
    if (!_d) { \
        asm volatile( \
            "{\n\t.reg .pred P1;\n\t" \
            "WL_%=:\n\t" \
            "mbarrier.try_wait.parity.acquire.cta.shared::cta.b64 P1, [%0], %1, 0x989680;\n\t" \
            "@P1 bra.uni WD_%=;\n\t" \
            "bra.uni WL_%=;\n\t" \
            "WD_%=:\n\t}" \
            :: "r"(_m), "r"(_p) : "memory"); \
    } \
} while(0)

// consumer-only named barrier (producers never touch id 1)
#define BAR_CONS() asm volatile("bar.sync 1, %0;" :: "n"(N_CONS) : "memory")

union BfU { __nv_bfloat162 b; uint32_t u; };

// Truncation split: hi = top-16-bits bf16 (exact), lo = x - hi (exact fp32) -> bf16 RN.
__device__ __forceinline__ void split_store(char* smem, uint32_t hi_off, uint32_t lo_off,
                                            int r, int q, float4 v) {
    uint32_t xu0 = __float_as_uint(v.x), xu1 = __float_as_uint(v.y);
    uint32_t xu2 = __float_as_uint(v.z), xu3 = __float_as_uint(v.w);
    uint32_t hi01 = (xu0 >> 16) | (xu1 & 0xFFFF0000u);
    uint32_t hi23 = (xu2 >> 16) | (xu3 & 0xFFFF0000u);
    float l0f = v.x - __uint_as_float(xu0 & 0xFFFF0000u);
    float l1f = v.y - __uint_as_float(xu1 & 0xFFFF0000u);
    float l2f = v.z - __uint_as_float(xu2 & 0xFFFF0000u);
    float l3f = v.w - __uint_as_float(xu3 & 0xFFFF0000u);
    BfU lo01, lo23;
    lo01.b = __floats2bfloat162_rn(l0f, l1f);
    lo23.b = __floats2bfloat162_rn(l2f, l3f);
    uint32_t boff = (uint32_t)r * 256u + (uint32_t)(((q >> 1) ^ (r & 7)) << 4)
                  + (uint32_t)((q & 1) << 3);
    *(uint2*)(smem + hi_off + boff) = make_uint2(hi01, hi23);
    *(uint2*)(smem + lo_off + boff) = make_uint2(lo01.u, lo23.u);
}

// ======= Kernel 0: row -> segment id =======
__global__ void __launch_bounds__(128)
fill_seg_kernel(const int* __restrict__ blk)
{
    int k = blockIdx.x;
    int s = blk[k], e = blk[k + 1];
    for (int i = s + threadIdx.x; i < e; i += 128)
        g_seg[i] = (unsigned short)k;
}

// ================= Kernel 1 (FUSED): scores + exp + weighted pool =================
// Consumers (warps 0-11): warp w owns m16 block (w>>1), n64 half (w&1) of each m96
// tile. After MMA: score halves -> smem, exp + segsum RED + raw-alpha write, then
// the weighted sum e*h accumulates straight from the SMEM A-slot (h = hi+lo,
// 2^-17 accurate) into h_file via atomicAdd. Slot released only after that.
// Producers (warps 12-15): LDG.cs -> split -> STS into 2-slot ring.
__global__ void __launch_bounds__(N_THREADS, 1)
score_kernel(const float* __restrict__ h, const float* __restrict__ W,
             const float* __restrict__ b, const float* __restrict__ ctx,
             float* __restrict__ h_file, float* __restrict__ alpha, int n)
{
    extern __shared__ char smem[];
    uint32_t sb = smem_to_u32(smem);
    int tid = threadIdx.x;
    int wid = tid >> 5, lane = tid & 31;

    // ---- prologue: W split (swizzled), transformed b/ctx, mbarriers ----
    for (int idx = tid; idx < 128 * 32; idx += N_THREADS) {
        int r = idx >> 5, q = idx & 31;
        float4 v = *(const float4*)(W + (size_t)r * DIM + q * 4);
        split_store(smem, OFF_W_HI, OFF_W_LO, r, q, v);
    }
    if (tid < DIM) {
        ((float*)(smem + OFF_BK))[tid] = b[tid] * K2LOG2E;
        ((float*)(smem + OFF_C2))[tid] = -2.0f * ctx[tid];
    }
    if (tid == 0) {
        #pragma unroll
        for (int s = 0; s < 2; s++) {
            MBARRIER_INIT(sb + OFF_MBAR + s * 8, N_PROD);        // full[s]
            MBARRIER_INIT(sb + OFF_MBAR + 16 + s * 8, N_CONS);   // empty[s]
        }
    }
    __syncthreads();

    int ntiles = (n + TILE96 - 1) / TILE96;

    if (wid >= 12) {
        // ================== PRODUCER (4 warps, 128 threads) ==================
        int ptid = tid - N_CONS;            // 0..127
        int ph[2] = {1, 1};                 // fresh-barrier: parity-1 wait passes
        for (int j = 0; ; j++) {
            long long tg = (long long)blockIdx.x + (long long)j * gridDim.x;
            if (tg >= ntiles) break;
            int slot = j & 1;
            MBARRIER_WAIT_PARITY(sb + OFF_MBAR + 16 + slot * 8, ph[slot]);
            ph[slot] ^= 1;
            uint32_t a_hi = OFF_SLOT0 + slot * SLOT_BYTES;
            uint32_t a_lo = a_hi + 24576;
            int m0 = (int)tg * TILE96;
            int valid = min(TILE96, n - m0);
            const float4* src = (const float4*)(h + (size_t)m0 * DIM);
            #pragma unroll
            for (int it = 0; it < 24; it++) {
                int chunk = ptid + it * N_PROD;   // 3072 chunks of 16B
                int r = chunk >> 5, q = chunk & 31;
                float4 v = (r < valid) ? __ldcs(src + chunk)
                                       : make_float4(0.f, 0.f, 0.f, 0.f);
                split_store(smem, a_hi, a_lo, r, q, v);
            }
            MBARRIER_ARRIVE(sb + OFF_MBAR + slot * 8);   // full[slot]
        }
    } else {
        // ================== CONSUMER (12 warps) ==================
        const float* bkp  = (const float*)(smem + OFF_BK);
        const float* c2p  = (const float*)(smem + OFF_C2);
        float*       sred = (float*)(smem + OFF_SRED);   // [2][96]
        float*       esp  = (float*)(smem + OFF_ES);     // [96]
        int mb  = wid >> 1;       // m16 block within m96 tile (0..5)
        int nbk = wid & 1;        // n64 half

        // csum: sum of ctx over this thread's 16 columns in its n64 half
        float csum = 0.f;
        {
            int cb = nbk * 64 + (lane & 3) * 2;
            #pragma unroll
            for (int j = 0; j < 8; j++)
                csum += ctx[cb + j * 8] + ctx[cb + j * 8 + 1];
        }

        int arow   = mb * 16 + (lane & 15);
        int brow0  = nbk * 64 + (lane & 7) + ((lane >> 4) << 3);
        int bk_sel = (lane >> 3) & 1;
        int ph[2] = {0, 0};

        // weighted-sum thread mapping: 4 cols per thread, 12 row-groups
        int wq = tid & 31;        // uint2 column group (cols wq*4..wq*4+3)
        int rg = tid >> 5;        // 0..11, rows rg, rg+12, ...
        uint32_t qoff = ((uint32_t)(wq & 1) << 3);
        uint32_t qx   = (uint32_t)(wq >> 1);

        for (int j = 0; ; j++) {
            long long tg = (long long)blockIdx.x + (long long)j * gridDim.x;
            if (tg >= ntiles) break;
            int slot = j & 1;
            MBARRIER_WAIT_PARITY(sb + OFF_MBAR + slot * 8, ph[slot]);   // full
            ph[slot] ^= 1;
            uint32_t a_hi_b = OFF_SLOT0 + slot * SLOT_BYTES;
            uint32_t a_lo_b = a_hi_b + 24576;
            int m0 = (int)tg * TILE96;
            int valid = min(TILE96, n - m0);

            float acc[8][4];
            #pragma unroll
            for (int jj = 0; jj < 8; jj++)
                #pragma unroll
                for (int e = 0; e < 4; e++) acc[jj][e] = 0.f;

            #pragma unroll
            for (int ks = 0; ks < 8; ks++) {
                uint32_t a_hi[4], a_lo[4];
                int akch = ks * 2 + (lane >> 4);
                ldsm4(a_hi, sw_addr(sb + a_hi_b, arow, akch));
                ldsm4(a_lo, sw_addr(sb + a_lo_b, arow, akch));
                int bkch = ks * 2 + bk_sel;
                #pragma unroll
                for (int p = 0; p < 4; p++) {
                    uint32_t bh[4], bl[4];
                    int br = brow0 + p * 16;
                    ldsm4(bh, sw_addr(sb + OFF_W_HI, br, bkch));
                    ldsm4(bl, sw_addr(sb + OFF_W_LO, br, bkch));
                    mma_bf16(acc[2 * p],     a_hi, bh);
                    mma_bf16(acc[2 * p],     a_lo, bh);
                    mma_bf16(acc[2 * p],     a_hi, bl);
                    mma_bf16(acc[2 * p + 1], a_hi, bh + 2);
                    mma_bf16(acc[2 * p + 1], a_lo, bh + 2);
                    mma_bf16(acc[2 * p + 1], a_hi, bl + 2);
                }
            }

            // score epilogue: tanh(x) = 1 - 2/(1+e^{2x})
            float s0 = csum, s1 = csum;
            #pragma unroll
            for (int jj = 0; jj < 8; jj++) {
                int c0 = nbk * 64 + jj * 8 + (lane & 3) * 2;
                float bk0 = bkp[c0], bk1 = bkp[c0 + 1];
                float c20 = c2p[c0], c21 = c2p[c0 + 1];
                s0 += rcpf(1.0f + ex2f(fmaf(acc[jj][0], K2LOG2E, bk0))) * c20
                    + rcpf(1.0f + ex2f(fmaf(acc[jj][1], K2LOG2E, bk1))) * c21;
                s1 += rcpf(1.0f + ex2f(fmaf(acc[jj][2], K2LOG2E, bk0))) * c20
                    + rcpf(1.0f + ex2f(fmaf(acc[jj][3], K2LOG2E, bk1))) * c21;
            }
            s0 += __shfl_xor_sync(0xffffffffu, s0, 1);
            s0 += __shfl_xor_sync(0xffffffffu, s0, 2);
            s1 += __shfl_xor_sync(0xffffffffu, s1, 1);
            s1 += __shfl_xor_sync(0xffffffffu, s1, 2);
            if ((lane & 3) == 0) {
                int r0 = mb * 16 + (lane >> 2);
                sred[nbk * 96 + r0]     = s0;
                sred[nbk * 96 + r0 + 8] = s1;
            }
            BAR_CONS();   // sred complete

            // exp + raw alpha + segment sum (threads 0..95, one row each)
            if (tid < 96) {
                int r = tid;
                float e = 0.f;
                if (r < valid) {
                    float s = sred[r] + sred[96 + r];
                    e = __expf(s);              // statistically overflow-safe
                    int m = m0 + r;
                    alpha[m] = e;               // raw; normalized in finalize
                    atomicAdd(&g_segsum[g_seg[m]], e);
                }
                esp[r] = e;
            }
            BAR_CONS();   // es complete

            // weighted pool: h_file[seg] += e * (hi + lo), straight from A-slot
            {
                float4 a4 = make_float4(0.f, 0.f, 0.f, 0.f);
                int kcur = -1;
                for (int r = rg; r < valid; r += 12) {
                    int kseg = g_seg[m0 + r];
                    if (kseg != kcur) {
                        if (kcur >= 0) {
                            float* dst = h_file + (size_t)kcur * DIM + wq * 4;
                            atomicAdd(dst + 0, a4.x);
                            atomicAdd(dst + 1, a4.y);
                            atomicAdd(dst + 2, a4.z);
                            atomicAdd(dst + 3, a4.w);
                            a4 = make_float4(0.f, 0.f, 0.f, 0.f);
                        }
                        kcur = kseg;
                    }
                    float e = esp[r];
                    uint32_t boff = (uint32_t)r * 256u
                                  + (((qx ^ (uint32_t)(r & 7)) << 4) | qoff);
                    uint2 hv = *(uint2*)(smem + a_hi_b + boff);
                    uint2 lv = *(uint2*)(smem + a_lo_b + boff);
                    float h0 = __uint_as_float(hv.x << 16)
                             + __uint_as_float(lv.x << 16);
                    float h1 = __uint_as_float(hv.x & 0xFFFF0000u)
                             + __uint_as_float(lv.x & 0xFFFF0000u);
                    float h2 = __uint_as_float(hv.y << 16)
                             + __uint_as_float(lv.y << 16);
                    float h3 = __uint_as_float(hv.y & 0xFFFF0000u)
                             + __uint_as_float(lv.y & 0xFFFF0000u);
                    a4.x = fmaf(e, h0, a4.x);
                    a4.y = fmaf(e, h1, a4.y);
                    a4.z = fmaf(e, h2, a4.z);
                    a4.w = fmaf(e, h3, a4.w);
                }
                if (kcur >= 0) {
                    float* dst = h_file + (size_t)kcur * DIM + wq * 4;
                    atomicAdd(dst + 0, a4.x);
                    atomicAdd(dst + 1, a4.y);
                    atomicAdd(dst + 2, a4.z);
                    atomicAdd(dst + 3, a4.w);
                }
            }

            // A-slot fully consumed (MMA + weighted pool) -> release
            MBARRIER_ARRIVE(sb + OFF_MBAR + 16 + slot * 8);   // empty[slot]
        }
    }
}

// ======= Kernel 2: finalize — normalize h_file rows and alpha by 1/segsum =======
__global__ void __launch_bounds__(128)
finalize_kernel(const int* __restrict__ blk, float* __restrict__ h_file,
                float* __restrict__ alpha)
{
    int k = blockIdx.x;
    int t = threadIdx.x;
    float sum = g_segsum[k];
    float inv = (sum > 0.f) ? 1.0f / sum : 0.f;
    h_file[(size_t)k * DIM + t] *= inv;    // empty segment: 0 * 0 = 0
    int s = blk[k], e = blk[k + 1];
    for (int i = s + t; i < e; i += 128)
        alpha[i] *= inv;
}

// ================= launch =================
extern "C" void kernel_launch(void* const* d_in, const int* in_sizes, int n_in,
                              void* d_out, int out_size)
{
    const float* h   = (const float*)d_in[0];
    const float* W   = (const float*)d_in[1];
    const float* b   = (const float*)d_in[2];
    const float* ctx = (const float*)d_in[3];
    const int*   blk = (const int*)d_in[4];

    int n = in_sizes[0] / DIM;
    if (n > MAX_N) n = MAX_N;
    int B = in_sizes[4] - 1;
    if (B > MAX_B) B = MAX_B;

    float* out    = (float*)d_out;
    float* h_file = out;
    float* alpha  = out + (size_t)B * DIM;

    cudaFuncSetAttribute(score_kernel,
                         cudaFuncAttributeMaxDynamicSharedMemorySize, SMEM_TOTAL);

    int dev = 0, nsm = 148;
    cudaGetDevice(&dev);
    cudaDeviceGetAttribute(&nsm, cudaDevAttrMultiProcessorCount, dev);

    // row->segment map + zeroed accumulators (all graph-capturable)
    fill_seg_kernel<<<B, 128>>>(blk);
    void* ss_ptr = nullptr;
    cudaGetSymbolAddress(&ss_ptr, g_segsum);
    cudaMemsetAsync(ss_ptr, 0, (size_t)B * sizeof(float));
    cudaMemsetAsync(h_file, 0, (size_t)B * DIM * sizeof(float));

    int ntiles = (n + TILE96 - 1) / TILE96;
    int grid1 = (nsm < ntiles) ? nsm : ntiles;

    score_kernel<<<grid1, N_THREADS, SMEM_TOTAL>>>(h, W, b, ctx, h_file, alpha, n);
    finalize_kernel<<<B, 128>>>(blk, h_file, alpha);
}

// round 15
// speedup vs baseline: 1.0150x; 1.0150x over previous
#include <cuda_runtime.h>
#include <cuda_bf16.h>
#include <cstdint>

#define DIM 128
#define TILE96 96
#define MAX_N 1000000
#define MAX_B 20000

__device__ unsigned short g_seg[MAX_N];   // row -> segment id
__device__ float g_segsum[MAX_B];         // per-segment sum of exp

// ---------------- smem layout (kernel 1) ----------------
// W_hi 32K | W_lo 32K | 2 A-slots (hi 24K + lo 24K) | bk | c2 | mbar | sred | es
#define OFF_W_HI   0
#define OFF_W_LO   32768
#define OFF_SLOT0  65536
#define SLOT_BYTES 49152
#define OFF_BK     163840          // b[c] * 2*log2(e)
#define OFF_C2     164352          // -2 * ctx[c]
#define OFF_MBAR   164864          // full[0..1] @ +0, scored[0..1] @ +16
#define OFF_SRED   164928          // float [2 slots][192] score halves
#define OFF_ES     166464          // float [2 slots][96] exp(score)
#define SMEM_TOTAL (166464 + 768 + 128)

#define N_CONS 384                 // 12 consumer warps (3 per SMSP)
#define N_PROD 128                 // 4 producer warps
#define N_THREADS (N_CONS + N_PROD)

#define K2LOG2E 2.8853900817779268f

// ---------------- helpers ----------------
__device__ __forceinline__ uint32_t smem_to_u32(const void* p) {
    uint32_t a;
    asm("{ .reg .u64 t; cvta.to.shared.u64 t, %1; cvt.u32.u64 %0, t; }"
        : "=r"(a) : "l"(p));
    return a;
}

__device__ __forceinline__ float ex2f(float x) {
    float y; asm("ex2.approx.f32 %0, %1;" : "=f"(y) : "f"(x)); return y;
}
__device__ __forceinline__ float rcpf(float x) {
    float y; asm("rcp.approx.f32 %0, %1;" : "=f"(y) : "f"(x)); return y;
}

// swizzled bf16 tile address: row-major, 256B/row (128 bf16), 16B chunks XOR'd by row&7
__device__ __forceinline__ uint32_t sw_addr(uint32_t base, int row, int kchunk) {
    return base + (uint32_t)row * 256u + (uint32_t)((kchunk ^ (row & 7)) << 4);
}

__device__ __forceinline__ void ldsm4(uint32_t* r, uint32_t addr) {
    asm volatile("ldmatrix.sync.aligned.m8n8.x4.shared.b16 {%0,%1,%2,%3}, [%4];"
        : "=r"(r[0]), "=r"(r[1]), "=r"(r[2]), "=r"(r[3]) : "r"(addr));
}

__device__ __forceinline__ void mma_bf16(float* d, const uint32_t* a, const uint32_t* b) {
    asm volatile(
        "mma.sync.aligned.m16n8k16.row.col.f32.bf16.bf16.f32 "
        "{%0,%1,%2,%3}, {%4,%5,%6,%7}, {%8,%9}, {%0,%1,%2,%3};"
        : "+f"(d[0]), "+f"(d[1]), "+f"(d[2]), "+f"(d[3])
        : "r"(a[0]), "r"(a[1]), "r"(a[2]), "r"(a[3]), "r"(b[0]), "r"(b[1]));
}

#define MBARRIER_INIT(mbar, count) \
    asm volatile("mbarrier.init.shared.b64 [%0], %1;" \
        :: "r"((uint32_t)(mbar)), "r"((uint32_t)(count)) : "memory")

#define MBARRIER_ARRIVE(mbar) \
    asm volatile("mbarrier.arrive.release.cta.shared.b64 _, [%0];" \
        :: "r"((uint32_t)(mbar)) : "memory")

#define MBARRIER_WAIT_PARITY(mbar, parity) do { \
    uint32_t _m = (uint32_t)(mbar), _p = (uint32_t)(parity), _d; \
    asm volatile( \
        "{\n\t.reg .pred p;\n\t" \
        "mbarrier.try_wait.parity.acquire.cta.shared::cta.b64 p, [%1], %2;\n\t" \
        "selp.b32 %0, 1, 0, p;\n\t}" \
        : "=r"(_d) : "r"(_m), "r"(_p) : "memory"); \
    if (!_d) { \
        asm volatile( \
            "{\n\t.reg .pred P1;\n\t" \
            "WL_%=:\n\t" \
            "mbarrier.try_wait.parity.acquire.cta.shared::cta.b64 P1, [%0], %1, 0x989680;\n\t" \
            "@P1 bra.uni WD_%=;\n\t" \
            "bra.uni WL_%=;\n\t" \
            "WD_%=:\n\t}" \
            :: "r"(_m), "r"(_p) : "memory"); \
    } \
} while(0)

// producer-only named barrier (consumers never touch id 2)
#define BAR_PROD() asm volatile("bar.sync 2, %0;" :: "n"(N_PROD) : "memory")

union BfU { __nv_bfloat162 b; uint32_t u; };

// Truncation split: hi = top-16-bits bf16 (exact), lo = x - hi (exact fp32) -> bf16 RN.
__device__ __forceinline__ void split_store(char* smem, uint32_t hi_off, uint32_t lo_off,
                                            int r, int q, float4 v) {
    uint32_t xu0 = __float_as_uint(v.x), xu1 = __float_as_uint(v.y);
    uint32_t xu2 = __float_as_uint(v.z), xu3 = __float_as_uint(v.w);
    uint32_t hi01 = (xu0 >> 16) | (xu1 & 0xFFFF0000u);
    uint32_t hi23 = (xu2 >> 16) | (xu3 & 0xFFFF0000u);
    float l0f = v.x - __uint_as_float(xu0 & 0xFFFF0000u);
    float l1f = v.y - __uint_as_float(xu1 & 0xFFFF0000u);
    float l2f = v.z - __uint_as_float(xu2 & 0xFFFF0000u);
    float l3f = v.w - __uint_as_float(xu3 & 0xFFFF0000u);
    BfU lo01, lo23;
    lo01.b = __floats2bfloat162_rn(l0f, l1f);
    lo23.b = __floats2bfloat162_rn(l2f, l3f);
    uint32_t boff = (uint32_t)r * 256u + (uint32_t)(((q >> 1) ^ (r & 7)) << 4)
                  + (uint32_t)((q & 1) << 3);
    *(uint2*)(smem + hi_off + boff) = make_uint2(hi01, hi23);
    *(uint2*)(smem + lo_off + boff) = make_uint2(lo01.u, lo23.u);
}

// ======= Kernel 0: row -> segment id =======
__global__ void __launch_bounds__(128)
fill_seg_kernel(const int* __restrict__ blk)
{
    int k = blockIdx.x;
    int s = blk[k], e = blk[k + 1];
    for (int i = s + threadIdx.x; i < e; i += 128)
        g_seg[i] = (unsigned short)k;
}

// Producer-side pool of one finished tile: exp + alpha + segsum, then
// h_file[seg] += e * (hi + lo) straight from the SMEM A-slot.
__device__ __forceinline__ void pool_tile(
    char* smem, int slot, int m0, int valid, int ptid,
    float* __restrict__ h_file, float* __restrict__ alpha)
{
    float* sred = (float*)(smem + OFF_SRED) + slot * 192;
    float* esp  = (float*)(smem + OFF_ES)   + slot * 96;
    uint32_t a_hi_b = OFF_SLOT0 + slot * SLOT_BYTES;
    uint32_t a_lo_b = a_hi_b + 24576;

    // stage A: exp + raw alpha + segment sum (threads 0..95, one row each)
    if (ptid < 96) {
        int r = ptid;
        float e = 0.f;
        if (r < valid) {
            float s = sred[r] + sred[96 + r];
            e = __expf(s);                  // statistically overflow-safe
            int m = m0 + r;
            alpha[m] = e;                   // raw; normalized in finalize
            atomicAdd(&g_segsum[g_seg[m]], e);
        }
        esp[r] = e;
    }
    BAR_PROD();

    // stage B: weighted pool, 128 threads: cols wq*4..+3, rows rg, rg+4, ...
    int wq = ptid & 31;
    int rg = ptid >> 5;
    uint32_t qoff = ((uint32_t)(wq & 1) << 3);
    uint32_t qx   = (uint32_t)(wq >> 1);

    float4 a4 = make_float4(0.f, 0.f, 0.f, 0.f);
    int kcur = -1;
    for (int r = rg; r < valid; r += 4) {
        int kseg = g_seg[m0 + r];
        if (kseg != kcur) {
            if (kcur >= 0) {
                float* dst = h_file + (size_t)kcur * DIM + wq * 4;
                atomicAdd(dst + 0, a4.x);
                atomicAdd(dst + 1, a4.y);
                atomicAdd(dst + 2, a4.z);
                atomicAdd(dst + 3, a4.w);
                a4 = make_float4(0.f, 0.f, 0.f, 0.f);
            }
            kcur = kseg;
        }
        float e = esp[r];
        uint32_t boff = (uint32_t)r * 256u
                      + (((qx ^ (uint32_t)(r & 7)) << 4) | qoff);
        uint2 hv = *(uint2*)(smem + a_hi_b + boff);
        uint2 lv = *(uint2*)(smem + a_lo_b + boff);
        float h0 = __uint_as_float(hv.x << 16) + __uint_as_float(lv.x << 16);
        float h1 = __uint_as_float(hv.x & 0xFFFF0000u)
                 + __uint_as_float(lv.x & 0xFFFF0000u);
        float h2 = __uint_as_float(hv.y << 16) + __uint_as_float(lv.y << 16);
        float h3 = __uint_as_float(hv.y & 0xFFFF0000u)
                 + __uint_as_float(lv.y & 0xFFFF0000u);
        a4.x = fmaf(e, h0, a4.x);
        a4.y = fmaf(e, h1, a4.y);
        a4.z = fmaf(e, h2, a4.z);
        a4.w = fmaf(e, h3, a4.w);
    }
    if (kcur >= 0) {
        float* dst = h_file + (size_t)kcur * DIM + wq * 4;
        atomicAdd(dst + 0, a4.x);
        atomicAdd(dst + 1, a4.y);
        atomicAdd(dst + 2, a4.z);
        atomicAdd(dst + 3, a4.w);
    }
}

// ================= Kernel 1 (FUSED, producer-side pooling) =======================
// Ring per slot: producer fills -> full -> consumers MMA + scores -> scored ->
// producer pools the tile (using its SMEM copy) then refills.
// Consumers (warps 0-11): MMA + tanh-dot epilogue + sred STS only.
// Producers (warps 12-15): pool previous tile, then LDG.cs -> split -> STS fill.
__global__ void __launch_bounds__(N_THREADS, 1)
score_kernel(const float* __restrict__ h, const float* __restrict__ W,
             const float* __restrict__ b, const float* __restrict__ ctx,
             float* __restrict__ h_file, float* __restrict__ alpha, int n)
{
    extern __shared__ char smem[];
    uint32_t sb = smem_to_u32(smem);
    int tid = threadIdx.x;
    int wid = tid >> 5, lane = tid & 31;

    // ---- prologue: W split (swizzled), transformed b/ctx, mbarriers ----
    for (int idx = tid; idx < 128 * 32; idx += N_THREADS) {
        int r = idx >> 5, q = idx & 31;
        float4 v = *(const float4*)(W + (size_t)r * DIM + q * 4);
        split_store(smem, OFF_W_HI, OFF_W_LO, r, q, v);
    }
    if (tid < DIM) {
        ((float*)(smem + OFF_BK))[tid] = b[tid] * K2LOG2E;
        ((float*)(smem + OFF_C2))[tid] = -2.0f * ctx[tid];
    }
    if (tid == 0) {
        #pragma unroll
        for (int s = 0; s < 2; s++) {
            MBARRIER_INIT(sb + OFF_MBAR + s * 8, N_PROD);        // full[s]
            MBARRIER_INIT(sb + OFF_MBAR + 16 + s * 8, N_CONS);   // scored[s]
        }
    }
    __syncthreads();

    int ntiles = (n + TILE96 - 1) / TILE96;

    if (wid >= 12) {
        // ================== PRODUCER (4 warps, 128 threads) ==================
        int ptid = tid - N_CONS;            // 0..127
        int ph[2] = {1, 1};                 // fresh-barrier: parity-1 wait passes
        int lastM0[2] = {-1, -1};
        int lastValid[2] = {0, 0};
        for (int j = 0; ; j++) {
            long long tg = (long long)blockIdx.x + (long long)j * gridDim.x;
            if (tg >= ntiles) break;
            int slot = j & 1;
            MBARRIER_WAIT_PARITY(sb + OFF_MBAR + 16 + slot * 8, ph[slot]);
            ph[slot] ^= 1;

            // pool the tile previously scored in this slot
            if (lastM0[slot] >= 0)
                pool_tile(smem, slot, lastM0[slot], lastValid[slot], ptid,
                          h_file, alpha);

            // refill slot with tile tg
            uint32_t a_hi = OFF_SLOT0 + slot * SLOT_BYTES;
            uint32_t a_lo = a_hi + 24576;
            int m0 = (int)tg * TILE96;
            int valid = min(TILE96, n - m0);
            const float4* src = (const float4*)(h + (size_t)m0 * DIM);
            #pragma unroll
            for (int it = 0; it < 24; it++) {
                int chunk = ptid + it * N_PROD;   // 3072 chunks of 16B
                int r = chunk >> 5, q = chunk & 31;
                float4 v = (r < valid) ? __ldcs(src + chunk)
                                       : make_float4(0.f, 0.f, 0.f, 0.f);
                split_store(smem, a_hi, a_lo, r, q, v);
            }
            MBARRIER_ARRIVE(sb + OFF_MBAR + slot * 8);   // full[slot]
            lastM0[slot] = m0;
            lastValid[slot] = valid;
        }
        // drain: pool the last tile(s) still in the ring
        #pragma unroll
        for (int s = 0; s < 2; s++) {
            if (lastM0[s] >= 0) {
                MBARRIER_WAIT_PARITY(sb + OFF_MBAR + 16 + s * 8, ph[s]);
                ph[s] ^= 1;
                pool_tile(smem, s, lastM0[s], lastValid[s], ptid,
                          h_file, alpha);
            }
        }
    } else {
        // ================== CONSUMER (12 warps) ==================
        const float* bkp = (const float*)(smem + OFF_BK);
        const float* c2p = (const float*)(smem + OFF_C2);
        int mb  = wid >> 1;       // m16 block within m96 tile (0..5)
        int nbk = wid & 1;        // n64 half

        // csum: sum of ctx over this thread's 16 columns in its n64 half
        float csum = 0.f;
        {
            int cb = nbk * 64 + (lane & 3) * 2;
            #pragma unroll
            for (int j = 0; j < 8; j++)
                csum += ctx[cb + j * 8] + ctx[cb + j * 8 + 1];
        }

        int arow   = mb * 16 + (lane & 15);
        int brow0  = nbk * 64 + (lane & 7) + ((lane >> 4) << 3);
        int bk_sel = (lane >> 3) & 1;
        int ph[2] = {0, 0};

        for (int j = 0; ; j++) {
            long long tg = (long long)blockIdx.x + (long long)j * gridDim.x;
            if (tg >= ntiles) break;
            int slot = j & 1;
            MBARRIER_WAIT_PARITY(sb + OFF_MBAR + slot * 8, ph[slot]);   // full
            ph[slot] ^= 1;
            uint32_t a_hi_b = OFF_SLOT0 + slot * SLOT_BYTES;
            uint32_t a_lo_b = a_hi_b + 24576;

            float acc[8][4];
            #pragma unroll
            for (int jj = 0; jj < 8; jj++)
                #pragma unroll
                for (int e = 0; e < 4; e++) acc[jj][e] = 0.f;

            #pragma unroll
            for (int ks = 0; ks < 8; ks++) {
                uint32_t a_hi[4], a_lo[4];
                int akch = ks * 2 + (lane >> 4);
                ldsm4(a_hi, sw_addr(sb + a_hi_b, arow, akch));
                ldsm4(a_lo, sw_addr(sb + a_lo_b, arow, akch));
                int bkch = ks * 2 + bk_sel;
                #pragma unroll
                for (int p = 0; p < 4; p++) {
                    uint32_t bh[4], bl[4];
                    int br = brow0 + p * 16;
                    ldsm4(bh, sw_addr(sb + OFF_W_HI, br, bkch));
                    ldsm4(bl, sw_addr(sb + OFF_W_LO, br, bkch));
                    mma_bf16(acc[2 * p],     a_hi, bh);
                    mma_bf16(acc[2 * p],     a_lo, bh);
                    mma_bf16(acc[2 * p],     a_hi, bl);
                    mma_bf16(acc[2 * p + 1], a_hi, bh + 2);
                    mma_bf16(acc[2 * p + 1], a_lo, bh + 2);
                    mma_bf16(acc[2 * p + 1], a_hi, bl + 2);
                }
            }

            // score epilogue: tanh(x) = 1 - 2/(1+e^{2x})
            float s0 = csum, s1 = csum;
            #pragma unroll
            for (int jj = 0; jj < 8; jj++) {
                int c0 = nbk * 64 + jj * 8 + (lane & 3) * 2;
                float bk0 = bkp[c0], bk1 = bkp[c0 + 1];
                float c20 = c2p[c0], c21 = c2p[c0 + 1];
                s0 += rcpf(1.0f + ex2f(fmaf(acc[jj][0], K2LOG2E, bk0))) * c20
                    + rcpf(1.0f + ex2f(fmaf(acc[jj][1], K2LOG2E, bk1))) * c21;
                s1 += rcpf(1.0f + ex2f(fmaf(acc[jj][2], K2LOG2E, bk0))) * c20
                    + rcpf(1.0f + ex2f(fmaf(acc[jj][3], K2LOG2E, bk1))) * c21;
            }
            s0 += __shfl_xor_sync(0xffffffffu, s0, 1);
            s0 += __shfl_xor_sync(0xffffffffu, s0, 2);
            s1 += __shfl_xor_sync(0xffffffffu, s1, 1);
            s1 += __shfl_xor_sync(0xffffffffu, s1, 2);
            if ((lane & 3) == 0) {
                float* sred = (float*)(smem + OFF_SRED) + slot * 192;
                int r0 = mb * 16 + (lane >> 2);
                sred[nbk * 96 + r0]     = s0;
                sred[nbk * 96 + r0 + 8] = s1;
            }
            // release: tile fully read (ldsm done) + scores staged
            MBARRIER_ARRIVE(sb + OFF_MBAR + 16 + slot * 8);   // scored[slot]
        }
    }
}

// ======= Kernel 2: finalize — normalize h_file rows and alpha by 1/segsum =======
__global__ void __launch_bounds__(128)
finalize_kernel(const int* __restrict__ blk, float* __restrict__ h_file,
                float* __restrict__ alpha)
{
    int k = blockIdx.x;
    int t = threadIdx.x;
    float sum = g_segsum[k];
    float inv = (sum > 0.f) ? 1.0f / sum : 0.f;
    h_file[(size_t)k * DIM + t] *= inv;    // empty segment: 0 * 0 = 0
    int s = blk[k], e = blk[k + 1];
    for (int i = s + t; i < e; i += 128)
        alpha[i] *= inv;
}

// ================= launch =================
extern "C" void kernel_launch(void* const* d_in, const int* in_sizes, int n_in,
                              void* d_out, int out_size)
{
    const float* h   = (const float*)d_in[0];
    const float* W   = (const float*)d_in[1];
    const float* b   = (const float*)d_in[2];
    const float* ctx = (const float*)d_in[3];
    const int*   blk = (const int*)d_in[4];

    int n = in_sizes[0] / DIM;
    if (n > MAX_N) n = MAX_N;
    int B = in_sizes[4] - 1;
    if (B > MAX_B) B = MAX_B;

    float* out    = (float*)d_out;
    float* h_file = out;
    float* alpha  = out + (size_t)B * DIM;

    cudaFuncSetAttribute(score_kernel,
                         cudaFuncAttributeMaxDynamicSharedMemorySize, SMEM_TOTAL);

    int dev = 0, nsm = 148;
    cudaGetDevice(&dev);
    cudaDeviceGetAttribute(&nsm, cudaDevAttrMultiProcessorCount, dev);

    // row->segment map + zeroed accumulators (all graph-capturable)
    fill_seg_kernel<<<B, 128>>>(blk);
    void* ss_ptr = nullptr;
    cudaGetSymbolAddress(&ss_ptr, g_segsum);
    cudaMemsetAsync(ss_ptr, 0, (size_t)B * sizeof(float));
    cudaMemsetAsync(h_file, 0, (size_t)B * DIM * sizeof(float));

    int ntiles = (n + TILE96 - 1) / TILE96;
    int grid1 = (nsm < ntiles) ? nsm : ntiles;

    score_kernel<<<grid1, N_THREADS, SMEM_TOTAL>>>(h, W, b, ctx, h_file, alpha, n);
    finalize_kernel<<<B, 128>>>(blk, h_file, alpha);
}

// round 16
// speedup vs baseline: 1.1480x; 1.1310x over previous
#include <cuda_runtime.h>
#include <cuda_bf16.h>
#include <cstdint>

#define DIM 128
#define TILE96 96
#define MAX_N 1000000
#define CHUNK 1024

__device__ float g_scores[MAX_N];

// ---------------- smem layout (kernel 1) ----------------
// W_hi 32K | W_lo 32K | 2 A-slots (hi 24K + lo 24K each) | bk | c2 | mbar
#define OFF_W_HI   0
#define OFF_W_LO   32768
#define OFF_SLOT0  65536
#define SLOT_BYTES 49152
#define OFF_BK     163840          // b[c] * 2*log2(e)
#define OFF_C2     164352          // -2 * ctx[c]
#define OFF_MBAR   164864          // full[0..1] @ +0, empty[0..1] @ +16
#define SMEM_TOTAL (164864 + 64)

#define N_CONS 384                 // 12 consumer warps (3 per SMSP)
#define N_PROD 128                 // 4 producer warps
#define N_THREADS (N_CONS + N_PROD)

#define K2LOG2E 2.8853900817779268f

// ---------------- helpers ----------------
__device__ __forceinline__ uint32_t smem_to_u32(const void* p) {
    uint32_t a;
    asm("{ .reg .u64 t; cvta.to.shared.u64 t, %1; cvt.u32.u64 %0, t; }"
        : "=r"(a) : "l"(p));
    return a;
}

__device__ __forceinline__ float ex2f(float x) {
    float y; asm("ex2.approx.f32 %0, %1;" : "=f"(y) : "f"(x)); return y;
}
__device__ __forceinline__ float rcpf(float x) {
    float y; asm("rcp.approx.f32 %0, %1;" : "=f"(y) : "f"(x)); return y;
}

// swizzled bf16 tile address: row-major, 256B/row (128 bf16), 16B chunks XOR'd by row&7
__device__ __forceinline__ uint32_t sw_addr(uint32_t base, int row, int kchunk) {
    return base + (uint32_t)row * 256u + (uint32_t)((kchunk ^ (row & 7)) << 4);
}

__device__ __forceinline__ void ldsm4(uint32_t* r, uint32_t addr) {
    asm volatile("ldmatrix.sync.aligned.m8n8.x4.shared.b16 {%0,%1,%2,%3}, [%4];"
        : "=r"(r[0]), "=r"(r[1]), "=r"(r[2]), "=r"(r[3]) : "r"(addr));
}

__device__ __forceinline__ void mma_bf16(float* d, const uint32_t* a, const uint32_t* b) {
    asm volatile(
        "mma.sync.aligned.m16n8k16.row.col.f32.bf16.bf16.f32 "
        "{%0,%1,%2,%3}, {%4,%5,%6,%7}, {%8,%9}, {%0,%1,%2,%3};"
        : "+f"(d[0]), "+f"(d[1]), "+f"(d[2]), "+f"(d[3])
        : "r"(a[0]), "r"(a[1]), "r"(a[2]), "r"(a[3]), "r"(b[0]), "r"(b[1]));
}

#define MBARRIER_INIT(mbar, count) \
    asm volatile("mbarrier.init.shared.b64 [%0], %1;" \
        :: "r"((uint32_t)(mbar)), "r"((uint32_t)(count)) : "memory")

#define MBARRIER_ARRIVE(mbar) \
    asm volatile("mbarrier.arrive.release.cta.shared.b64 _, [%0];" \
        :: "r"((uint32_t)(mbar)) : "memory")

#define MBARRIER_WAIT_PARITY(mbar, parity) do { \
    uint32_t _m = (uint32_t)(mbar), _p = (uint32_t)(parity), _d; \
    asm volatile( \
        "{\n\t.reg .pred p;\n\t" \
        "mbarrier.try_wait.parity.acquire.cta.shared::cta.b64 p, [%1], %2;\n\t" \
        "selp.b32 %0, 1, 0, p;\n\t}" \
        : "=r"(_d) : "r"(_m), "r"(_p) : "memory"); \
    if (!_d) { \
        asm volatile( \
            "{\n\t.reg .pred P1;\n\t" \
            "WL_%=:\n\t" \
            "mbarrier.try_wait.parity.acquire.cta.shared::cta.b64 P1, [%0], %1, 0x989680;\n\t" \
            "@P1 bra.uni WD_%=;\n\t" \
            "bra.uni WL_%=;\n\t" \
            "WD_%=:\n\t}" \
            :: "r"(_m), "r"(_p) : "memory"); \
    } \
} while(0)

union BfU { __nv_bfloat162 b; uint32_t u; };

// Truncation split: hi = top-16-bits bf16 (exact), lo = x - hi (exact fp32) -> bf16 RN.
__device__ __forceinline__ void split_store(char* smem, uint32_t hi_off, uint32_t lo_off,
                                            int r, int q, float4 v) {
    uint32_t xu0 = __float_as_uint(v.x), xu1 = __float_as_uint(v.y);
    uint32_t xu2 = __float_as_uint(v.z), xu3 = __float_as_uint(v.w);
    uint32_t hi01 = (xu0 >> 16) | (xu1 & 0xFFFF0000u);
    uint32_t hi23 = (xu2 >> 16) | (xu3 & 0xFFFF0000u);
    float l0f = v.x - __uint_as_float(xu0 & 0xFFFF0000u);
    float l1f = v.y - __uint_as_float(xu1 & 0xFFFF0000u);
    float l2f = v.z - __uint_as_float(xu2 & 0xFFFF0000u);
    float l3f = v.w - __uint_as_float(xu3 & 0xFFFF0000u);
    BfU lo01, lo23;
    lo01.b = __floats2bfloat162_rn(l0f, l1f);
    lo23.b = __floats2bfloat162_rn(l2f, l3f);
    uint32_t boff = (uint32_t)r * 256u + (uint32_t)(((q >> 1) ^ (r & 7)) << 4)
                  + (uint32_t)((q & 1) << 3);
    *(uint2*)(smem + hi_off + boff) = make_uint2(hi01, hi23);
    *(uint2*)(smem + lo_off + boff) = make_uint2(lo01.u, lo23.u);
}

// ================= Kernel 1: 16 warps, 3 consumer warps per SMSP (R13) ==========
// Consumers (warps 0-11): warp w owns m16 block (w>>1) of the m96 tile, n64 half
// (w&1). Producers (warps 12-15): LDG.cs -> split -> STS into 2-slot ring.
__global__ void __launch_bounds__(N_THREADS, 1)
score_kernel(const float* __restrict__ h, const float* __restrict__ W,
             const float* __restrict__ b, const float* __restrict__ ctx, int n)
{
    extern __shared__ char smem[];
    uint32_t sb = smem_to_u32(smem);
    int tid = threadIdx.x;
    int wid = tid >> 5, lane = tid & 31;

    // ---- prologue: W split (swizzled), transformed b/ctx, mbarriers ----
    for (int idx = tid; idx < 128 * 32; idx += N_THREADS) {
        int r = idx >> 5, q = idx & 31;
        float4 v = *(const float4*)(W + (size_t)r * DIM + q * 4);
        split_store(smem, OFF_W_HI, OFF_W_LO, r, q, v);
    }
    if (tid < DIM) {
        ((float*)(smem + OFF_BK))[tid] = b[tid] * K2LOG2E;
        ((float*)(smem + OFF_C2))[tid] = -2.0f * ctx[tid];
    }
    if (tid == 0) {
        #pragma unroll
        for (int s = 0; s < 2; s++) {
            MBARRIER_INIT(sb + OFF_MBAR + s * 8, N_PROD);        // full[s]
            MBARRIER_INIT(sb + OFF_MBAR + 16 + s * 8, N_CONS);   // empty[s]
        }
    }
    __syncthreads();

    int ntiles = (n + TILE96 - 1) / TILE96;

    if (wid >= 12) {
        // ================== PRODUCER (4 warps, 128 threads) ==================
        int ptid = tid - N_CONS;            // 0..127
        int ph[2] = {1, 1};                 // fresh-barrier: parity-1 wait passes
        for (int j = 0; ; j++) {
            long long tg = (long long)blockIdx.x + (long long)j * gridDim.x;
            if (tg >= ntiles) break;
            int slot = j & 1;
            MBARRIER_WAIT_PARITY(sb + OFF_MBAR + 16 + slot * 8, ph[slot]);
            ph[slot] ^= 1;
            uint32_t a_hi = OFF_SLOT0 + slot * SLOT_BYTES;
            uint32_t a_lo = a_hi + 24576;
            int m0 = (int)tg * TILE96;
            int valid = min(TILE96, n - m0);
            const float4* src = (const float4*)(h + (size_t)m0 * DIM);
            #pragma unroll
            for (int it = 0; it < 24; it++) {
                int chunk = ptid + it * N_PROD;   // 3072 chunks of 16B
                int r = chunk >> 5, q = chunk & 31;
                float4 v = (r < valid) ? __ldcs(src + chunk)
                                       : make_float4(0.f, 0.f, 0.f, 0.f);
                split_store(smem, a_hi, a_lo, r, q, v);
            }
            MBARRIER_ARRIVE(sb + OFF_MBAR + slot * 8);   // full[slot]
        }
    } else {
        // ================== CONSUMER (12 warps) ==================
        const float* bkp = (const float*)(smem + OFF_BK);
        const float* c2p = (const float*)(smem + OFF_C2);
        int mb  = wid >> 1;       // m16 block within m96 tile (0..5)
        int nbk = wid & 1;        // n64 half

        // csum: sum of ctx over this thread's 16 columns in its n64 half
        float csum = 0.f;
        {
            int cb = nbk * 64 + (lane & 3) * 2;
            #pragma unroll
            for (int j = 0; j < 8; j++)
                csum += ctx[cb + j * 8] + ctx[cb + j * 8 + 1];
        }

        int arow   = mb * 16 + (lane & 15);
        int brow0  = nbk * 64 + (lane & 7) + ((lane >> 4) << 3);
        int bk_sel = (lane >> 3) & 1;
        int ph[2] = {0, 0};

        for (int j = 0; ; j++) {
            long long tg = (long long)blockIdx.x + (long long)j * gridDim.x;
            if (tg >= ntiles) break;
            int slot = j & 1;
            MBARRIER_WAIT_PARITY(sb + OFF_MBAR + slot * 8, ph[slot]);   // full
            ph[slot] ^= 1;
            uint32_t a_hi_b = OFF_SLOT0 + slot * SLOT_BYTES;
            uint32_t a_lo_b = a_hi_b + 24576;

            float acc[8][4];
            #pragma unroll
            for (int jj = 0; jj < 8; jj++)
                #pragma unroll
                for (int e = 0; e < 4; e++) acc[jj][e] = 0.f;

            #pragma unroll
            for (int ks = 0; ks < 8; ks++) {
                uint32_t a_hi[4], a_lo[4];
                int akch = ks * 2 + (lane >> 4);
                ldsm4(a_hi, sw_addr(sb + a_hi_b, arow, akch));
                ldsm4(a_lo, sw_addr(sb + a_lo_b, arow, akch));
                int bkch = ks * 2 + bk_sel;
                #pragma unroll
                for (int p = 0; p < 4; p++) {
                    uint32_t bh[4], bl[4];
                    int br = brow0 + p * 16;
                    ldsm4(bh, sw_addr(sb + OFF_W_HI, br, bkch));
                    ldsm4(bl, sw_addr(sb + OFF_W_LO, br, bkch));
                    mma_bf16(acc[2 * p],     a_hi, bh);
                    mma_bf16(acc[2 * p],     a_lo, bh);
                    mma_bf16(acc[2 * p],     a_hi, bl);
                    mma_bf16(acc[2 * p + 1], a_hi, bh + 2);
                    mma_bf16(acc[2 * p + 1], a_lo, bh + 2);
                    mma_bf16(acc[2 * p + 1], a_hi, bl + 2);
                }
            }

            // release slot (epilogue uses only registers + const smem)
            MBARRIER_ARRIVE(sb + OFF_MBAR + 16 + slot * 8);   // empty

            // epilogue: tanh(x) = 1 - 2/(1+e^{2x}); 3 FFMA + EX2 + RCP per elem
            float s0 = csum, s1 = csum;
            #pragma unroll
            for (int jj = 0; jj < 8; jj++) {
                int c0 = nbk * 64 + jj * 8 + (lane & 3) * 2;
                float bk0 = bkp[c0], bk1 = bkp[c0 + 1];
                float c20 = c2p[c0], c21 = c2p[c0 + 1];
                s0 += rcpf(1.0f + ex2f(fmaf(acc[jj][0], K2LOG2E, bk0))) * c20
                    + rcpf(1.0f + ex2f(fmaf(acc[jj][1], K2LOG2E, bk1))) * c21;
                s1 += rcpf(1.0f + ex2f(fmaf(acc[jj][2], K2LOG2E, bk0))) * c20
                    + rcpf(1.0f + ex2f(fmaf(acc[jj][3], K2LOG2E, bk1))) * c21;
            }
            s0 += __shfl_xor_sync(0xffffffffu, s0, 1);
            s0 += __shfl_xor_sync(0xffffffffu, s0, 2);
            s1 += __shfl_xor_sync(0xffffffffu, s1, 1);
            s1 += __shfl_xor_sync(0xffffffffu, s1, 2);
            if ((lane & 3) == 0) {
                int m = (int)tg * TILE96 + mb * 16 + (lane >> 2);
                if (m < n)     atomicAdd(&g_scores[m], s0);
                if (m + 8 < n) atomicAdd(&g_scores[m + 8], s1);
            }
        }
    }
}

// ======= Kernel 2a: per-segment softmax stats (warp-per-segment, 4/CTA) ========
__global__ void __launch_bounds__(128)
seg_stats_kernel(const int* __restrict__ blk, float* __restrict__ h_file,
                 float* __restrict__ alpha, int B)
{
    int k = blockIdx.x * 4 + (threadIdx.x >> 5);
    int lid = threadIdx.x & 31;
    if (k >= B) return;
    int s = blk[k], e = blk[k + 1];

    // zero h_file row: 32 lanes x float4 = 512B
    ((float4*)(h_file + (size_t)k * DIM))[lid] = make_float4(0.f, 0.f, 0.f, 0.f);
    if (e - s <= 0) return;

    // pass 1: max (warp-local)
    float m = -3.402823466e38f;
    for (int i = s + lid; i < e; i += 32) m = fmaxf(m, g_scores[i]);
    #pragma unroll
    for (int o = 16; o; o >>= 1) m = fmaxf(m, __shfl_xor_sync(0xffffffffu, m, o));

    // pass 2: sum of exp; stash raw exp into alpha
    float sum = 0.f;
    for (int i = s + lid; i < e; i += 32) {
        float ev = __expf(g_scores[i] - m);
        alpha[i] = ev;
        sum += ev;
    }
    #pragma unroll
    for (int o = 16; o; o >>= 1) sum += __shfl_xor_sync(0xffffffffu, sum, o);
    float inv = 1.0f / sum;

    // pass 3: normalize in place (each lane rescales exactly what it wrote)
    for (int i = s + lid; i < e; i += 32) alpha[i] *= inv;
}

// ======= Kernel 2b: uniform-chunk weighted accumulation (256 thr, 8 rows MLP) ===
__global__ void __launch_bounds__(256)
accum_kernel(const float* __restrict__ h, const int* __restrict__ blk,
             const float* __restrict__ alpha, float* __restrict__ h_file,
             int n, int B)
{
    int r0 = blockIdx.x * CHUNK;
    int r1 = min(n, r0 + CHUNK);
    if (r0 >= r1) return;
    int t = threadIdx.x;
    int wr = t >> 5;          // 0..7: row offset within 8-row group
    int q  = t & 31;          // float4 column index

    // largest k with blk[k] <= r0
    int lo = 0, hi = B - 1;
    while (lo < hi) {
        int mid = (lo + hi + 1) >> 1;
        if (blk[mid] <= r0) lo = mid; else hi = mid - 1;
    }
    int k = lo;
    int nend = blk[k + 1];

    float4 acc = make_float4(0.f, 0.f, 0.f, 0.f);
    int i = r0;
    while (true) {
        int stop = min(r1, nend);
        #pragma unroll 4
        for (; i + 8 <= stop; i += 8) {
            int r = i + wr;
            float a = __ldcs(alpha + r);                 // warp-uniform broadcast
            float4 hv = __ldcs((const float4*)(h + (size_t)r * DIM) + q);
            acc.x = fmaf(a, hv.x, acc.x);
            acc.y = fmaf(a, hv.y, acc.y);
            acc.z = fmaf(a, hv.z, acc.z);
            acc.w = fmaf(a, hv.w, acc.w);
        }
        if (i < stop) {                                   // 1-7 remainder rows
            int r = i + wr;
            if (r < stop) {
                float a = __ldcs(alpha + r);
                float4 hv = __ldcs((const float4*)(h + (size_t)r * DIM) + q);
                acc.x = fmaf(a, hv.x, acc.x);
                acc.y = fmaf(a, hv.y, acc.y);
                acc.z = fmaf(a, hv.z, acc.z);
                acc.w = fmaf(a, hv.w, acc.w);
            }
            i = stop;
        }
        if (stop < r1) {
            float* dst = h_file + (size_t)k * DIM + q * 4;
            atomicAdd(dst + 0, acc.x);
            atomicAdd(dst + 1, acc.y);
            atomicAdd(dst + 2, acc.z);
            atomicAdd(dst + 3, acc.w);
            acc = make_float4(0.f, 0.f, 0.f, 0.f);
            do { k++; } while (blk[k + 1] <= stop);
            nend = blk[k + 1];
        } else break;
    }
    float* dst = h_file + (size_t)k * DIM + q * 4;
    atomicAdd(dst + 0, acc.x);
    atomicAdd(dst + 1, acc.y);
    atomicAdd(dst + 2, acc.z);
    atomicAdd(dst + 3, acc.w);
}

// ================= launch =================
extern "C" void kernel_launch(void* const* d_in, const int* in_sizes, int n_in,
                              void* d_out, int out_size)
{
    const float* h   = (const float*)d_in[0];
    const float* W   = (const float*)d_in[1];
    const float* b   = (const float*)d_in[2];
    const float* ctx = (const float*)d_in[3];
    const int*   blk = (const int*)d_in[4];

    int n = in_sizes[0] / DIM;
    if (n > MAX_N) n = MAX_N;
    int B = in_sizes[4] - 1;

    float* out    = (float*)d_out;
    float* h_file = out;
    float* alpha  = out + (size_t)B * DIM;

    cudaFuncSetAttribute(score_kernel,
                         cudaFuncAttributeMaxDynamicSharedMemorySize, SMEM_TOTAL);

    int dev = 0, nsm = 148;
    cudaGetDevice(&dev);
    cudaDeviceGetAttribute(&nsm, cudaDevAttrMultiProcessorCount, dev);

    // zero the score accumulator (RED targets); graph-capturable memset node
    void* sc_ptr = nullptr;
    cudaGetSymbolAddress(&sc_ptr, g_scores);
    cudaMemsetAsync(sc_ptr, 0, (size_t)n * sizeof(float));

    int ntiles = (n + TILE96 - 1) / TILE96;
    int grid1 = (nsm < ntiles) ? nsm : ntiles;

    score_kernel<<<grid1, N_THREADS, SMEM_TOTAL>>>(h, W, b, ctx, n);
    seg_stats_kernel<<<(B + 3) / 4, 128>>>(blk, h_file, alpha, B);
    int gridB = (n + CHUNK - 1) / CHUNK;
    accum_kernel<<<gridB, 256>>>(h, blk, alpha, h_file, n, B);
}